// round 13
// baseline (speedup 1.0000x reference)
#include <cuda_runtime.h>
#include <cstdint>
#include <cstddef>

// ----------------------------------------------------------------------------
// 2-layer GRU (inverted update), B=64, S=512, I=512, H=1024, O=2.
// ONE persistent kernel (grid=128 CTAs x 256 thr) runs all 512 steps with a
// software grid barrier. Activations/hidden are TRANSPOSED: [feature][batch].
// Weights pre-transposed to [K][N] (r|z fused along N). Each GEMM phase =
// 128 units (16 n-tiles x 8 k-slices or 8 x 16); partials -> fixed-order
// reduce (deterministic) fusing bias + sigmoid/tanh + GRU state update.
// fp32 math via packed fma.rn.f32x2 (2 FLOP-pairs/instr).
// ----------------------------------------------------------------------------

#define GRID 128

// ---------------- device scratch (static; no allocation APIs) ----------------
__device__ __align__(256) float g_xT[(size_t)512 * 512 * 64];   // [t][k][m]
__device__ __align__(256) float g_WA0T[(size_t)1536 * 2048];    // [k][n] (r|z)
__device__ __align__(256) float g_WC0T[(size_t)1536 * 1024];
__device__ __align__(256) float g_WA1T[(size_t)2048 * 2048];
__device__ __align__(256) float g_WC1T[(size_t)2048 * 1024];
__device__ __align__(256) float g_part[(size_t)16 * 1024 * 64]; // == 8*2048*64
__device__ __align__(256) float g_h0[1024 * 64];
__device__ __align__(256) float g_h1[1024 * 64];
__device__ __align__(256) float g_hr0[1024 * 64];
__device__ __align__(256) float g_zs0[1024 * 64];
__device__ __align__(256) float g_hr1[1024 * 64];
__device__ __align__(256) float g_zs1[1024 * 64];

__device__ unsigned int g_bar_cnt;   // zero-initialized at module load
__device__ unsigned int g_bar_gen;

// ---------------- small device helpers ----------------
__device__ __forceinline__ void cp16(float* s, const float* g) {
    uint32_t sa = (uint32_t)__cvta_generic_to_shared(s);
    asm volatile("cp.async.cg.shared.global [%0], [%1], 16;" :: "r"(sa), "l"(g));
}
__device__ __forceinline__ unsigned long long dup2(float w) {
    unsigned long long d;
    asm("mov.b64 %0, {%1, %1};" : "=l"(d) : "f"(w));
    return d;
}
__device__ __forceinline__ void ffma2(unsigned long long& c, unsigned long long a,
                                      unsigned long long b) {
    asm("fma.rn.f32x2 %0, %1, %2, %0;" : "+l"(c) : "l"(a), "l"(b));
}
__device__ __forceinline__ float sigmoidf_(float x) { return 1.f / (1.f + expf(-x)); }

__device__ __forceinline__ unsigned ld_acq(unsigned* p) {
    unsigned v;
    asm volatile("ld.acquire.gpu.b32 %0, [%1];" : "=r"(v) : "l"(p));
    return v;
}
__device__ __forceinline__ void st_rel(unsigned* p, unsigned v) {
    asm volatile("st.release.gpu.b32 [%0], %1;" :: "l"(p), "r"(v));
}

// Software grid barrier (sense via monotone generation counter).
__device__ __forceinline__ void gridsync() {
    __syncthreads();
    if (threadIdx.x == 0) {
        unsigned gen = ld_acq(&g_bar_gen);   // read BEFORE arrive
        __threadfence();                      // publish CTA's prior writes
        unsigned n = atomicAdd(&g_bar_cnt, 1u);
        if (n == GRID - 1) {
            g_bar_cnt = 0;                    // ordered before release below
            st_rel(&g_bar_gen, gen + 1u);
        } else {
            while (ld_acq(&g_bar_gen) == gen) { }
        }
    }
    __syncthreads();
}

// ---------------- GEMM unit: one 64(m) x 128(n) tile over one K slice --------
// Source A rows: [0,kSplit) from A1, [kSplit,..) from A2 (both [k][64]).
// All k chunk boundaries are multiples of 32, kSplit multiple of 32.
__device__ __noinline__ void gemm_unit(
    const float* __restrict__ A1, const float* __restrict__ A2, int kSplit,
    const float* __restrict__ WT, int N, int n0, int k0, int nchunks,
    float* __restrict__ partBase)
{
    __shared__ float As[2][32 * 64];    // 16 KB
    __shared__ float Ws[2][32 * 128];   // 32 KB

    const int t  = threadIdx.x;
    const int tm = t & 7;     // 8 m-groups of 8
    const int tn = t >> 3;    // 32 n-groups of 4

    // prefetch chunk 0
    {
        const float* a = (k0 < kSplit) ? (A1 + (size_t)k0 * 64)
                                       : (A2 + (size_t)(k0 - kSplit) * 64);
        const float* w = WT + (size_t)k0 * N + n0;
        #pragma unroll
        for (int i = 0; i < 2; i++) { int idx = t + i * 256; cp16(&As[0][idx * 4], a + idx * 4); }
        #pragma unroll
        for (int i = 0; i < 4; i++) {
            int idx = t + i * 256, kk = idx >> 5, c4 = idx & 31;
            cp16(&Ws[0][idx * 4], w + (size_t)kk * N + c4 * 4);
        }
        asm volatile("cp.async.commit_group;" ::: "memory");
    }

    unsigned long long acc[4][4];
    #pragma unroll
    for (int j = 0; j < 4; j++)
        #pragma unroll
        for (int p = 0; p < 4; p++) acc[j][p] = 0ull;

    for (int c = 0; c < nchunks; c++) {
        const int buf = c & 1;
        if (c + 1 < nchunks) {
            int k = k0 + (c + 1) * 32;
            const float* a = (k < kSplit) ? (A1 + (size_t)k * 64)
                                          : (A2 + (size_t)(k - kSplit) * 64);
            const float* w = WT + (size_t)k * N + n0;
            #pragma unroll
            for (int i = 0; i < 2; i++) { int idx = t + i * 256; cp16(&As[buf ^ 1][idx * 4], a + idx * 4); }
            #pragma unroll
            for (int i = 0; i < 4; i++) {
                int idx = t + i * 256, kk = idx >> 5, c4 = idx & 31;
                cp16(&Ws[buf ^ 1][idx * 4], w + (size_t)kk * N + c4 * 4);
            }
            asm volatile("cp.async.commit_group;" ::: "memory");
            asm volatile("cp.async.wait_group 1;" ::: "memory");
        } else {
            asm volatile("cp.async.wait_group 0;" ::: "memory");
        }
        __syncthreads();

        const float* as = &As[buf][0] + tm * 8;
        const float* ws = &Ws[buf][0] + tn * 4;
        #pragma unroll 8
        for (int k = 0; k < 32; k++) {
            unsigned long long a0 = *(const unsigned long long*)(as + k * 64 + 0);
            unsigned long long a1 = *(const unsigned long long*)(as + k * 64 + 2);
            unsigned long long a2 = *(const unsigned long long*)(as + k * 64 + 4);
            unsigned long long a3 = *(const unsigned long long*)(as + k * 64 + 6);
            float4 w = *(const float4*)(ws + k * 128);
            unsigned long long d;
            d = dup2(w.x); ffma2(acc[0][0], a0, d); ffma2(acc[0][1], a1, d);
                           ffma2(acc[0][2], a2, d); ffma2(acc[0][3], a3, d);
            d = dup2(w.y); ffma2(acc[1][0], a0, d); ffma2(acc[1][1], a1, d);
                           ffma2(acc[1][2], a2, d); ffma2(acc[1][3], a3, d);
            d = dup2(w.z); ffma2(acc[2][0], a0, d); ffma2(acc[2][1], a1, d);
                           ffma2(acc[2][2], a2, d); ffma2(acc[2][3], a3, d);
            d = dup2(w.w); ffma2(acc[3][0], a0, d); ffma2(acc[3][1], a1, d);
                           ffma2(acc[3][2], a2, d); ffma2(acc[3][3], a3, d);
        }
        __syncthreads();
    }

    // epilogue: partial tile, layout [n][m]
    #pragma unroll
    for (int j = 0; j < 4; j++) {
        int n = tn * 4 + j;
        float* p = partBase + (size_t)n * 64 + tm * 8;
        float2 x0 = *(float2*)&acc[j][0], x1 = *(float2*)&acc[j][1];
        float2 x2 = *(float2*)&acc[j][2], x3 = *(float2*)&acc[j][3];
        *(float4*)(p + 0) = make_float4(x0.x, x0.y, x1.x, x1.y);
        *(float4*)(p + 4) = make_float4(x2.x, x2.y, x3.x, x3.y);
    }
}

// -------- reduce (gate phase): r,z = sigmoid(.); hr = h*r; zs = z -----------
__device__ __forceinline__ void reduce_gates(
    int nsl, int N2, const float* __restrict__ br, const float* __restrict__ bz,
    const float* __restrict__ h, float* __restrict__ hr, float* __restrict__ zs)
{
    int gid = blockIdx.x * 256 + threadIdx.x;
    if (gid < 16384) {
        int n  = gid >> 4;
        int m4 = (gid & 15) << 2;
        float4 sr = make_float4(0.f, 0.f, 0.f, 0.f);
        float4 sz = make_float4(0.f, 0.f, 0.f, 0.f);
        #pragma unroll 4
        for (int s = 0; s < nsl; s++) {
            const float* p = g_part + (size_t)s * N2 * 64;
            float4 a = *(const float4*)(p + (size_t)n * 64 + m4);
            float4 b = *(const float4*)(p + (size_t)(1024 + n) * 64 + m4);
            sr.x += a.x; sr.y += a.y; sr.z += a.z; sr.w += a.w;
            sz.x += b.x; sz.y += b.y; sz.z += b.z; sz.w += b.w;
        }
        float rb = br[n], zb = bz[n];
        float4 hv = *(const float4*)(h + (size_t)n * 64 + m4);
        float4 r, z, o;
        r.x = sigmoidf_(sr.x + rb); r.y = sigmoidf_(sr.y + rb);
        r.z = sigmoidf_(sr.z + rb); r.w = sigmoidf_(sr.w + rb);
        z.x = sigmoidf_(sz.x + zb); z.y = sigmoidf_(sz.y + zb);
        z.z = sigmoidf_(sz.z + zb); z.w = sigmoidf_(sz.w + zb);
        o.x = hv.x * r.x; o.y = hv.y * r.y; o.z = hv.z * r.z; o.w = hv.w * r.w;
        *(float4*)(hr + (size_t)n * 64 + m4) = o;
        *(float4*)(zs + (size_t)n * 64 + m4) = z;
    }
}

// -------- reduce (candidate phase): c = tanh(.); h = h*z + (1-z)*c ----------
__device__ __forceinline__ void reduce_can(
    int nsl, const float* __restrict__ bc,
    const float* __restrict__ zs, float* __restrict__ h)
{
    int gid = blockIdx.x * 256 + threadIdx.x;
    if (gid < 16384) {
        int n  = gid >> 4;
        int m4 = (gid & 15) << 2;
        float4 sc = make_float4(0.f, 0.f, 0.f, 0.f);
        #pragma unroll 4
        for (int s = 0; s < nsl; s++) {
            const float* p = g_part + (size_t)s * 1024 * 64;
            float4 a = *(const float4*)(p + (size_t)n * 64 + m4);
            sc.x += a.x; sc.y += a.y; sc.z += a.z; sc.w += a.w;
        }
        float cb = bc[n];
        float4 z  = *(const float4*)(zs + (size_t)n * 64 + m4);
        float4 hv = *(const float4*)(h + (size_t)n * 64 + m4);
        float4 c;
        c.x = tanhf(sc.x + cb); c.y = tanhf(sc.y + cb);
        c.z = tanhf(sc.z + cb); c.w = tanhf(sc.w + cb);
        float4 o;
        o.x = hv.x * z.x + (1.f - z.x) * c.x;
        o.y = hv.y * z.y + (1.f - z.y) * c.y;
        o.z = hv.z * z.z + (1.f - z.z) * c.z;
        o.w = hv.w * z.w + (1.f - z.w) * c.w;
        *(float4*)(h + (size_t)n * 64 + m4) = o;
    }
}

// ---------------- persistent kernel: full recurrence ----------------
__global__ void __launch_bounds__(256, 1) gru_persist(
    const float* __restrict__ br0, const float* __restrict__ bz0, const float* __restrict__ bc0,
    const float* __restrict__ br1, const float* __restrict__ bz1, const float* __restrict__ bc1,
    const float* __restrict__ Wreg, const float* __restrict__ breg,
    float* __restrict__ out)
{
    const int cta = blockIdx.x;

    // zero initial hidden state (every launch — deterministic)
    for (int i = cta * 256 + threadIdx.x; i < 1024 * 64; i += GRID * 256) {
        g_h0[i] = 0.f;
        g_h1[i] = 0.f;
    }
    gridsync();

    for (int t = 0; t < 512; t++) {
        const float* xt = g_xT + (size_t)t * 512 * 64;

        // Phase A: layer0 gates r|z, N=2048, K=1536 (16 n-tiles x 8 k-slices of 192)
        {
            int nt = cta >> 3, ks = cta & 7;
            gemm_unit(xt, g_h0, 512, g_WA0T, 2048, nt * 128, ks * 192, 6,
                      g_part + (size_t)ks * 2048 * 64 + (size_t)nt * 128 * 64);
        }
        gridsync();
        reduce_gates(8, 2048, br0, bz0, g_h0, g_hr0, g_zs0);
        gridsync();

        // Phase B: layer0 candidate, N=1024, K=1536 (8 n-tiles x 16 k-slices of 96)
        {
            int nt = cta >> 4, ks = cta & 15;
            gemm_unit(xt, g_hr0, 512, g_WC0T, 1024, nt * 128, ks * 96, 3,
                      g_part + (size_t)ks * 1024 * 64 + (size_t)nt * 128 * 64);
        }
        gridsync();
        reduce_can(16, bc0, g_zs0, g_h0);
        gridsync();

        // Phase C: layer1 gates r|z, N=2048, K=2048 (16 x 8 slices of 256)
        {
            int nt = cta >> 3, ks = cta & 7;
            gemm_unit(g_h0, g_h1, 1024, g_WA1T, 2048, nt * 128, ks * 256, 8,
                      g_part + (size_t)ks * 2048 * 64 + (size_t)nt * 128 * 64);
        }
        gridsync();
        reduce_gates(8, 2048, br1, bz1, g_h1, g_hr1, g_zs1);
        gridsync();

        // Phase D: layer1 candidate, N=1024, K=2048 (8 x 16 slices of 128)
        {
            int nt = cta >> 4, ks = cta & 15;
            gemm_unit(g_h0, g_hr1, 1024, g_WC1T, 1024, nt * 128, ks * 128, 4,
                      g_part + (size_t)ks * 1024 * 64 + (size_t)nt * 128 * 64);
        }
        gridsync();
        reduce_can(16, bc1, g_zs1, g_h1);
        gridsync();
    }

    // regressor: out[m][o] = sum_n h1[n][m] * Wreg[o][n] + breg[o]
    if (cta == 0 && threadIdx.x < 128) {
        int o = threadIdx.x >> 6, m = threadIdx.x & 63;
        float s0 = 0.f, s1 = 0.f, s2 = 0.f, s3 = 0.f;
        #pragma unroll 4
        for (int n = 0; n < 1024; n += 4) {
            s0 += g_h1[(size_t)(n + 0) * 64 + m] * Wreg[o * 1024 + n + 0];
            s1 += g_h1[(size_t)(n + 1) * 64 + m] * Wreg[o * 1024 + n + 1];
            s2 += g_h1[(size_t)(n + 2) * 64 + m] * Wreg[o * 1024 + n + 2];
            s3 += g_h1[(size_t)(n + 3) * 64 + m] * Wreg[o * 1024 + n + 3];
        }
        out[m * 2 + o] = s0 + s1 + s2 + s3 + breg[o];
    }
}

// -------- x transpose: x[B=64][S=512][I=512] -> xT[t][k][m] --------
__global__ void xtrans_k(const float* __restrict__ x, float* __restrict__ xT)
{
    __shared__ float tile[64][33];
    int tp = blockIdx.y;
    int k0 = blockIdx.x * 32;
    int tx = threadIdx.x, ty = threadIdx.y;   // (32, 8)
    #pragma unroll
    for (int i = 0; i < 8; i++) {
        int m = ty + i * 8;
        tile[m][tx] = x[((size_t)m * 512 + tp) * 512 + k0 + tx];
    }
    __syncthreads();
    #pragma unroll
    for (int i = 0; i < 4; i++) {
        int k = ty + i * 8;
        #pragma unroll
        for (int j = 0; j < 2; j++) {
            int m = j * 32 + tx;
            xT[((size_t)tp * 512 + k0 + k) * 64 + m] = tile[m][k];
        }
    }
}

// -------- weight transpose: W[R][C] -> dst[k][n0+r], row stride dstStride ----
__global__ void wtrans_k(const float* __restrict__ W, int C,
                         float* __restrict__ dst, int dstStride, int n0)
{
    __shared__ float tile[32][33];
    int c0 = blockIdx.x * 32, r0 = blockIdx.y * 32;
    int tx = threadIdx.x, ty = threadIdx.y;   // (32, 8)
    #pragma unroll
    for (int i = 0; i < 4; i++) {
        int r = r0 + ty + i * 8;
        tile[ty + i * 8][tx] = W[(size_t)r * C + c0 + tx];
    }
    __syncthreads();
    #pragma unroll
    for (int i = 0; i < 4; i++) {
        int k = c0 + ty + i * 8;
        dst[(size_t)k * dstStride + n0 + r0 + tx] = tile[tx][ty + i * 8];
    }
}

// ---------------- host ----------------
static float* symaddr(const void* sym) {
    void* p = nullptr;
    cudaGetSymbolAddress(&p, sym);
    return (float*)p;
}

extern "C" void kernel_launch(void* const* d_in, const int* in_sizes, int n_in,
                              void* d_out, int out_size)
{
    const float* x    = (const float*)d_in[0];
    const float* Wr0  = (const float*)d_in[1];
    const float* br0  = (const float*)d_in[2];
    const float* Wz0  = (const float*)d_in[3];
    const float* bz0  = (const float*)d_in[4];
    const float* Wc0  = (const float*)d_in[5];
    const float* bc0  = (const float*)d_in[6];
    const float* Wr1  = (const float*)d_in[7];
    const float* br1  = (const float*)d_in[8];
    const float* Wz1  = (const float*)d_in[9];
    const float* bz1  = (const float*)d_in[10];
    const float* Wc1  = (const float*)d_in[11];
    const float* bc1  = (const float*)d_in[12];
    const float* Wreg = (const float*)d_in[13];
    const float* breg = (const float*)d_in[14];

    float* xT   = symaddr(g_xT);
    float* WA0T = symaddr(g_WA0T);
    float* WC0T = symaddr(g_WC0T);
    float* WA1T = symaddr(g_WA1T);
    float* WC1T = symaddr(g_WC1T);

    dim3 tb(32, 8);
    xtrans_k<<<dim3(16, 512), tb>>>(x, xT);
    wtrans_k<<<dim3(48, 32), tb>>>(Wr0, 1536, WA0T, 2048, 0);
    wtrans_k<<<dim3(48, 32), tb>>>(Wz0, 1536, WA0T, 2048, 1024);
    wtrans_k<<<dim3(48, 32), tb>>>(Wc0, 1536, WC0T, 1024, 0);
    wtrans_k<<<dim3(64, 32), tb>>>(Wr1, 2048, WA1T, 2048, 0);
    wtrans_k<<<dim3(64, 32), tb>>>(Wz1, 2048, WA1T, 2048, 1024);
    wtrans_k<<<dim3(64, 32), tb>>>(Wc1, 2048, WC1T, 1024, 0);

    gru_persist<<<GRID, 256>>>(br0, bz0, bc0, br1, bz1, bc1,
                               Wreg, breg, (float*)d_out);
}

// round 14
// speedup vs baseline: 1.1163x; 1.1163x over previous
#include <cuda_runtime.h>
#include <cstdint>
#include <cstddef>

// ----------------------------------------------------------------------------
// 2-layer GRU (inverted update), B=64, S=512, I=512, H=1024, O=2.
// ONE persistent kernel (128 CTAs x 256 thr) + software grid barrier.
// GEMMs on the tensor pipe: mma.sync.m16n8k8 tf32, 3-pass hi/lo split
// (ah*bh + ah*bl + al*bh) for ~fp32 accuracy.
// Native layouts: activations [batch][k], weights [n][k]; no transposes.
// Split-K partials in fixed order -> deterministic fused reduces
// (bias + sigmoid/tanh + GRU update + tf32 re-split of new state).
// ----------------------------------------------------------------------------

#define GRID 128
#define KC   16    // k per smem chunk (2 k8 steps)
#define APAD 18    // act smem row length in float2 (16 + 2 pad)
#define WPAD 18    // wgt smem row length in float2

// ---------------- device scratch (static; no allocation APIs) ----------------
__device__ __align__(256) float g_xp[(size_t)512 * 64 * 512 * 2];  // [t][b][i][hi,lo]
__device__ __align__(256) float g_WA0p[(size_t)2048 * 1536 * 2];   // [n][k][hi,lo], r|z
__device__ __align__(256) float g_WC0p[(size_t)1024 * 1536 * 2];
__device__ __align__(256) float g_WA1p[(size_t)2048 * 2048 * 2];
__device__ __align__(256) float g_WC1p[(size_t)1024 * 2048 * 2];
__device__ __align__(256) float g_part[(size_t)8 * 64 * 2048];     // == 16*64*1024
__device__ __align__(256) float g_h0[64 * 1024];
__device__ __align__(256) float g_h1[64 * 1024];
__device__ __align__(256) float g_h0p[64 * 1024 * 2];
__device__ __align__(256) float g_h1p[64 * 1024 * 2];
__device__ __align__(256) float g_hr0p[64 * 1024 * 2];
__device__ __align__(256) float g_hr1p[64 * 1024 * 2];
__device__ __align__(256) float g_zs0[64 * 1024];
__device__ __align__(256) float g_zs1[64 * 1024];

__device__ unsigned g_bar_cnt;   // zero-initialized at module load
__device__ unsigned g_bar_gen;

// ---------------- helpers ----------------
__device__ __forceinline__ void cp16(void* s, const void* g) {
    uint32_t sa = (uint32_t)__cvta_generic_to_shared(s);
    asm volatile("cp.async.cg.shared.global [%0], [%1], 16;" :: "r"(sa), "l"(g));
}
__device__ __forceinline__ float sigmoidf_(float x) { return 1.f / (1.f + expf(-x)); }

// split fp32 -> (tf32 hi, tf32 lo) with v ~= hi + lo
__device__ __forceinline__ float2 tf32split(float v) {
    uint32_t hu;
    asm("cvt.rna.tf32.f32 %0, %1;" : "=r"(hu) : "f"(v));
    float hi = __uint_as_float(hu);
    float lo = v - hi;
    uint32_t lu;
    asm("cvt.rna.tf32.f32 %0, %1;" : "=r"(lu) : "f"(lo));
    return make_float2(hi, __uint_as_float(lu));
}

__device__ __forceinline__ void mma8(float& d0, float& d1, float& d2, float& d3,
                                     const uint32_t a[4], uint32_t b0, uint32_t b1) {
    asm volatile(
        "mma.sync.aligned.m16n8k8.row.col.f32.tf32.tf32.f32 "
        "{%0,%1,%2,%3},{%4,%5,%6,%7},{%8,%9},{%0,%1,%2,%3};"
        : "+f"(d0), "+f"(d1), "+f"(d2), "+f"(d3)
        : "r"(a[0]), "r"(a[1]), "r"(a[2]), "r"(a[3]), "r"(b0), "r"(b1));
}

__device__ __forceinline__ unsigned ld_acq(unsigned* p) {
    unsigned v;
    asm volatile("ld.acquire.gpu.b32 %0, [%1];" : "=r"(v) : "l"(p));
    return v;
}
__device__ __forceinline__ void st_rel(unsigned* p, unsigned v) {
    asm volatile("st.release.gpu.b32 [%0], %1;" :: "l"(p), "r"(v));
}

__device__ __forceinline__ void gridsync() {
    __syncthreads();
    if (threadIdx.x == 0) {
        unsigned gen = ld_acq(&g_bar_gen);
        __threadfence();
        unsigned n = atomicAdd(&g_bar_cnt, 1u);
        if (n == GRID - 1) {
            g_bar_cnt = 0;
            st_rel(&g_bar_gen, gen + 1u);
        } else {
            while (ld_acq(&g_bar_gen) == gen) { }
        }
    }
    __syncthreads();
}

// ---------------- GEMM unit: 64(batch) x 128(feat) tile over one K slice -----
// A (mma A operand) = activations [b][k] (hi/lo pairs), rows from A1 (k<kSplit)
// else A2. B (mma B operand) = weights [n][k] pairs, Wt = tile base (128 rows).
// Result partial: partBase[m][n], row stride Nld. k0/KC boundaries aligned.
__device__ __forceinline__ void gemm_unit(
    float2* __restrict__ sAs, float2* __restrict__ sWs,
    const float2* __restrict__ A1, int ldA1,
    const float2* __restrict__ A2, int ldA2, int kSplit,
    const float2* __restrict__ Wt, int K,
    int k0, int nchunks, float* __restrict__ partBase, int Nld)
{
    const int t = threadIdx.x;
    const int w = t >> 5, l = t & 31;
    const int mb  = (w & 3) * 16 + (l >> 2);   // batch row for A frags
    const int fhl = (w >> 2) * 64 + (l >> 2);  // feat col base for B frags
    const int kq  = l & 3;

    // prefetch chunk 0 into buffer 0
    {
        const float2* ab  = (k0 < kSplit) ? (A1 + k0) : (A2 + (k0 - kSplit));
        const int     lda = (k0 < kSplit) ? ldA1 : ldA2;
        #pragma unroll
        for (int i = 0; i < 2; i++) {
            int idx = t + i * 256, r = idx >> 3, c = idx & 7;
            cp16(sAs + r * APAD + c * 2, ab + (size_t)r * lda + c * 2);
        }
        const float2* wb = Wt + k0;
        #pragma unroll
        for (int i = 0; i < 4; i++) {
            int idx = t + i * 256, r = idx >> 3, c = idx & 7;
            cp16(sWs + r * WPAD + c * 2, wb + (size_t)r * K + c * 2);
        }
        asm volatile("cp.async.commit_group;" ::: "memory");
    }

    float acc[8][4];
    #pragma unroll
    for (int j = 0; j < 8; j++)
        #pragma unroll
        for (int e = 0; e < 4; e++) acc[j][e] = 0.f;

    for (int c = 0; c < nchunks; c++) {
        const int buf = c & 1;
        if (c + 1 < nchunks) {
            int k = k0 + (c + 1) * KC;
            const float2* ab  = (k < kSplit) ? (A1 + k) : (A2 + (k - kSplit));
            const int     lda = (k < kSplit) ? ldA1 : ldA2;
            float2* dA = sAs + (buf ^ 1) * (64 * APAD);
            float2* dW = sWs + (buf ^ 1) * (128 * WPAD);
            #pragma unroll
            for (int i = 0; i < 2; i++) {
                int idx = t + i * 256, r = idx >> 3, cc = idx & 7;
                cp16(dA + r * APAD + cc * 2, ab + (size_t)r * lda + cc * 2);
            }
            const float2* wb = Wt + k;
            #pragma unroll
            for (int i = 0; i < 4; i++) {
                int idx = t + i * 256, r = idx >> 3, cc = idx & 7;
                cp16(dW + r * WPAD + cc * 2, wb + (size_t)r * K + cc * 2);
            }
            asm volatile("cp.async.commit_group;" ::: "memory");
            asm volatile("cp.async.wait_group 1;" ::: "memory");
        } else {
            asm volatile("cp.async.wait_group 0;" ::: "memory");
        }
        __syncthreads();

        const float2* as = sAs + buf * (64 * APAD);
        const float2* ws = sWs + buf * (128 * WPAD);
        #pragma unroll
        for (int q = 0; q < 2; q++) {
            uint32_t ah[4], al[4];
            #pragma unroll
            for (int e = 0; e < 4; e++) {
                float2 v = as[(mb + 8 * (e & 1)) * APAD + q * 8 + kq + 4 * (e >> 1)];
                ah[e] = __float_as_uint(v.x);
                al[e] = __float_as_uint(v.y);
            }
            #pragma unroll
            for (int j = 0; j < 8; j++) {
                const float2* wp = ws + (fhl + j * 8) * WPAD + q * 8 + kq;
                float2 b0 = wp[0], b1 = wp[4];
                uint32_t bh0 = __float_as_uint(b0.x), bl0 = __float_as_uint(b0.y);
                uint32_t bh1 = __float_as_uint(b1.x), bl1 = __float_as_uint(b1.y);
                mma8(acc[j][0], acc[j][1], acc[j][2], acc[j][3], ah, bh0, bh1);
                mma8(acc[j][0], acc[j][1], acc[j][2], acc[j][3], ah, bl0, bl1);
                mma8(acc[j][0], acc[j][1], acc[j][2], acc[j][3], al, bh0, bh1);
            }
        }
        __syncthreads();
    }

    // epilogue: D rows = batch (m), cols = feat (n)
    const int m0 = (w & 3) * 16 + (l >> 2);
    const int c0 = (w >> 2) * 64 + 2 * (l & 3);
    #pragma unroll
    for (int j = 0; j < 8; j++) {
        *(float2*)&partBase[(size_t)m0 * Nld + c0 + j * 8] =
            make_float2(acc[j][0], acc[j][1]);
        *(float2*)&partBase[(size_t)(m0 + 8) * Nld + c0 + j * 8] =
            make_float2(acc[j][2], acc[j][3]);
    }
}

// -------- reduce (gate phase): r,z = sigmoid(.); hr_pair = split(h*r); zs = z --
__device__ __forceinline__ void reduce_gates(
    int nsl, int N2, const float* __restrict__ br, const float* __restrict__ bz,
    const float* __restrict__ h, float* __restrict__ hrp, float* __restrict__ zs)
{
    int gid = blockIdx.x * 256 + threadIdx.x;
    if (gid >= 16384) return;
    int m = gid >> 8, n = (gid & 255) << 2;
    float4 sr = make_float4(0.f, 0.f, 0.f, 0.f);
    float4 sz = make_float4(0.f, 0.f, 0.f, 0.f);
    #pragma unroll 4
    for (int s = 0; s < nsl; s++) {
        const float* p = g_part + (size_t)s * 64 * N2 + (size_t)m * N2;
        float4 a = *(const float4*)(p + n);
        float4 b = *(const float4*)(p + 1024 + n);
        sr.x += a.x; sr.y += a.y; sr.z += a.z; sr.w += a.w;
        sz.x += b.x; sz.y += b.y; sz.z += b.z; sz.w += b.w;
    }
    float4 rb = *(const float4*)(br + n);
    float4 zb = *(const float4*)(bz + n);
    float4 hv = *(const float4*)(h + (size_t)m * 1024 + n);
    float rx = sigmoidf_(sr.x + rb.x), ry = sigmoidf_(sr.y + rb.y);
    float rz = sigmoidf_(sr.z + rb.z), rw = sigmoidf_(sr.w + rb.w);
    float zx = sigmoidf_(sz.x + zb.x), zy = sigmoidf_(sz.y + zb.y);
    float zz = sigmoidf_(sz.z + zb.z), zw = sigmoidf_(sz.w + zb.w);
    float2 p0 = tf32split(hv.x * rx), p1 = tf32split(hv.y * ry);
    float2 p2 = tf32split(hv.z * rz), p3 = tf32split(hv.w * rw);
    float* d = hrp + ((size_t)m * 1024 + n) * 2;
    *(float4*)(d)     = make_float4(p0.x, p0.y, p1.x, p1.y);
    *(float4*)(d + 4) = make_float4(p2.x, p2.y, p3.x, p3.y);
    *(float4*)(zs + (size_t)m * 1024 + n) = make_float4(zx, zy, zz, zw);
}

// -------- reduce (cand phase): c = tanh(.); h = h*z+(1-z)*c; hp = split(h) ----
__device__ __forceinline__ void reduce_can(
    int nsl, const float* __restrict__ bc,
    const float* __restrict__ zs, float* __restrict__ h, float* __restrict__ hp)
{
    int gid = blockIdx.x * 256 + threadIdx.x;
    if (gid >= 16384) return;
    int m = gid >> 8, n = (gid & 255) << 2;
    float4 sc = make_float4(0.f, 0.f, 0.f, 0.f);
    #pragma unroll 4
    for (int s = 0; s < nsl; s++) {
        const float* p = g_part + (size_t)s * 64 * 1024 + (size_t)m * 1024;
        float4 a = *(const float4*)(p + n);
        sc.x += a.x; sc.y += a.y; sc.z += a.z; sc.w += a.w;
    }
    float4 cb = *(const float4*)(bc + n);
    float4 z  = *(const float4*)(zs + (size_t)m * 1024 + n);
    float4 hv = *(const float4*)(h  + (size_t)m * 1024 + n);
    float cx = tanhf(sc.x + cb.x), cy = tanhf(sc.y + cb.y);
    float cz = tanhf(sc.z + cb.z), cw = tanhf(sc.w + cb.w);
    float4 o;
    o.x = hv.x * z.x + (1.f - z.x) * cx;
    o.y = hv.y * z.y + (1.f - z.y) * cy;
    o.z = hv.z * z.z + (1.f - z.z) * cz;
    o.w = hv.w * z.w + (1.f - z.w) * cw;
    *(float4*)(h + (size_t)m * 1024 + n) = o;
    float2 p0 = tf32split(o.x), p1 = tf32split(o.y);
    float2 p2 = tf32split(o.z), p3 = tf32split(o.w);
    float* d = hp + ((size_t)m * 1024 + n) * 2;
    *(float4*)(d)     = make_float4(p0.x, p0.y, p1.x, p1.y);
    *(float4*)(d + 4) = make_float4(p2.x, p2.y, p3.x, p3.y);
}

// ---------------- persistent kernel ----------------
__global__ void __launch_bounds__(256, 1) gru_persist(
    const float* __restrict__ br0, const float* __restrict__ bz0, const float* __restrict__ bc0,
    const float* __restrict__ br1, const float* __restrict__ bz1, const float* __restrict__ bc1,
    const float* __restrict__ Wreg, const float* __restrict__ breg,
    float* __restrict__ out)
{
    extern __shared__ __align__(16) char smem_raw[];
    float2* sAs = (float2*)smem_raw;                 // 2 x 64 x APAD
    float2* sWs = sAs + 2 * 64 * APAD;               // 2 x 128 x WPAD

    const int cta = blockIdx.x;

    for (int i = cta * 256 + threadIdx.x; i < 64 * 1024; i += GRID * 256) {
        g_h0[i] = 0.f;
        g_h1[i] = 0.f;
    }
    for (int i = cta * 256 + threadIdx.x; i < 64 * 1024 * 2; i += GRID * 256) {
        g_h0p[i] = 0.f;
        g_h1p[i] = 0.f;
    }
    gridsync();

    for (int t = 0; t < 512; t++) {
        const float2* xp_t = (const float2*)g_xp + (size_t)t * 64 * 512;

        // Phase A: layer0 gates r|z (N=2048, K=1536; 16 feat-tiles x 8 k-slices)
        {
            int ft = cta >> 3, s = cta & 7;
            gemm_unit(sAs, sWs, xp_t, 512, (const float2*)g_h0p, 1024, 512,
                      (const float2*)g_WA0p + (size_t)ft * 128 * 1536, 1536,
                      s * 192, 12,
                      g_part + (size_t)s * 64 * 2048 + ft * 128, 2048);
        }
        gridsync();
        reduce_gates(8, 2048, br0, bz0, g_h0, g_hr0p, g_zs0);
        gridsync();

        // Phase B: layer0 candidate (N=1024, K=1536; 8 x 16)
        {
            int ft = cta >> 4, s = cta & 15;
            gemm_unit(sAs, sWs, xp_t, 512, (const float2*)g_hr0p, 1024, 512,
                      (const float2*)g_WC0p + (size_t)ft * 128 * 1536, 1536,
                      s * 96, 6,
                      g_part + (size_t)s * 64 * 1024 + ft * 128, 1024);
        }
        gridsync();
        reduce_can(16, bc0, g_zs0, g_h0, g_h0p);
        gridsync();

        // Phase C: layer1 gates r|z (N=2048, K=2048; 16 x 8)
        {
            int ft = cta >> 3, s = cta & 7;
            gemm_unit(sAs, sWs, (const float2*)g_h0p, 1024,
                      (const float2*)g_h1p, 1024, 1024,
                      (const float2*)g_WA1p + (size_t)ft * 128 * 2048, 2048,
                      s * 256, 16,
                      g_part + (size_t)s * 64 * 2048 + ft * 128, 2048);
        }
        gridsync();
        reduce_gates(8, 2048, br1, bz1, g_h1, g_hr1p, g_zs1);
        gridsync();

        // Phase D: layer1 candidate (N=1024, K=2048; 8 x 16)
        {
            int ft = cta >> 4, s = cta & 15;
            gemm_unit(sAs, sWs, (const float2*)g_h0p, 1024,
                      (const float2*)g_hr1p, 1024, 1024,
                      (const float2*)g_WC1p + (size_t)ft * 128 * 2048, 2048,
                      s * 128, 8,
                      g_part + (size_t)s * 64 * 1024 + ft * 128, 1024);
        }
        gridsync();
        reduce_can(16, bc1, g_zs1, g_h1, g_h1p);
        gridsync();
    }

    // regressor: out[m][o] = sum_n h1[m][n] * Wreg[o][n] + breg[o]
    if (cta == 0 && threadIdx.x < 128) {
        int o = threadIdx.x >> 6, m = threadIdx.x & 63;
        const float* hr = g_h1 + (size_t)m * 1024;
        const float* wr = Wreg + (size_t)o * 1024;
        float s0 = 0.f, s1 = 0.f, s2 = 0.f, s3 = 0.f;
        #pragma unroll 4
        for (int n = 0; n < 1024; n += 4) {
            s0 += hr[n + 0] * wr[n + 0];
            s1 += hr[n + 1] * wr[n + 1];
            s2 += hr[n + 2] * wr[n + 2];
            s3 += hr[n + 3] * wr[n + 3];
        }
        out[m * 2 + o] = s0 + s1 + s2 + s3 + breg[o];
    }
}

// ---------------- prep kernels ----------------
// x[b][t][i] -> g_xp[t][b][i][hi,lo]
__global__ void xprep_k(const float* __restrict__ x)
{
    size_t idx = (size_t)blockIdx.x * 256 + threadIdx.x;   // 64*512*512
    int b = (int)(idx >> 18);
    int t = (int)((idx >> 9) & 511);
    int i = (int)(idx & 511);
    float2 p = tf32split(x[idx]);
    ((float2*)g_xp)[((size_t)t * 64 + b) * 512 + i] = p;
}

// weights -> [n][k][hi,lo], r|z concatenated along n
__global__ void wprep_k(const float* __restrict__ Wr0, const float* __restrict__ Wz0,
                        const float* __restrict__ Wc0, const float* __restrict__ Wr1,
                        const float* __restrict__ Wz1, const float* __restrict__ Wc1)
{
    const float* src; float* dst; int K; size_t n0;
    switch (blockIdx.y) {
        case 0:  src = Wr0; dst = g_WA0p; K = 1536; n0 = 0;    break;
        case 1:  src = Wz0; dst = g_WA0p; K = 1536; n0 = 1024; break;
        case 2:  src = Wc0; dst = g_WC0p; K = 1536; n0 = 0;    break;
        case 3:  src = Wr1; dst = g_WA1p; K = 2048; n0 = 0;    break;
        case 4:  src = Wz1; dst = g_WA1p; K = 2048; n0 = 1024; break;
        default: src = Wc1; dst = g_WC1p; K = 2048; n0 = 0;    break;
    }
    size_t e = (size_t)blockIdx.x * 256 + threadIdx.x;
    if (e >= (size_t)1024 * K) return;
    ((float2*)dst)[n0 * K + e] = tf32split(src[e]);
}

// ---------------- host ----------------
extern "C" void kernel_launch(void* const* d_in, const int* in_sizes, int n_in,
                              void* d_out, int out_size)
{
    const float* x    = (const float*)d_in[0];
    const float* Wr0  = (const float*)d_in[1];
    const float* br0  = (const float*)d_in[2];
    const float* Wz0  = (const float*)d_in[3];
    const float* bz0  = (const float*)d_in[4];
    const float* Wc0  = (const float*)d_in[5];
    const float* bc0  = (const float*)d_in[6];
    const float* Wr1  = (const float*)d_in[7];
    const float* br1  = (const float*)d_in[8];
    const float* Wz1  = (const float*)d_in[9];
    const float* bz1  = (const float*)d_in[10];
    const float* Wc1  = (const float*)d_in[11];
    const float* bc1  = (const float*)d_in[12];
    const float* Wreg = (const float*)d_in[13];
    const float* breg = (const float*)d_in[14];

    static int smem_set = 0;
    const int smem_bytes = (2 * 64 * APAD + 2 * 128 * WPAD) * (int)sizeof(float2); // 55296
    if (!smem_set) {
        cudaFuncSetAttribute(gru_persist,
                             cudaFuncAttributeMaxDynamicSharedMemorySize, smem_bytes);
        smem_set = 1;
    }

    xprep_k<<<65536, 256>>>(x);
    wprep_k<<<dim3(8192, 6), 256>>>(Wr0, Wz0, Wc0, Wr1, Wz1, Wc1);
    gru_persist<<<GRID, 256, smem_bytes>>>(br0, bz0, bc0, br1, bz1, bc1,
                                           Wreg, breg, (float*)d_out);
}

// round 15
// speedup vs baseline: 1.1491x; 1.0294x over previous
#include <cuda_runtime.h>
#include <cstdint>
#include <cstddef>

// ----------------------------------------------------------------------------
// 2-layer GRU (inverted update), B=64, S=512, I=512, H=1024, O=2.
// Kernel 1 (xproj): xg[t][b][3072] = x_t @ [Wr0|Wz0|Wc0][:, :512].T + bias
// Kernel 2 (persist, 128 CTAs): 512 steps; per step 4 GEMM phases on the
// tensor pipe (mma.m16n8k8 tf32, 3-pass hi/lo split done post-LDS from fp32
// smem), per-tile epoch counters for gemm->reduce ordering, 4 grid barriers
// per step. Weights read directly from harness buffers ([n][k] native).
// Deterministic: fixed-order reductions, no float atomics.
// ----------------------------------------------------------------------------

#define GRID 128
#define KC 64
#define RA_STRIDE 68
#define RW_STRIDE 68
#define PA_STRIDE 136
#define PW_STRIDE 136

#define SM_RAWA  0
#define SM_RAWW  (2 * 64 * RA_STRIDE)
#define SM_PAIRA (SM_RAWW + 2 * 128 * RW_STRIDE)
#define SM_PAIRW (SM_PAIRA + 64 * PA_STRIDE)
#define SM_TOTAL (SM_PAIRW + 128 * PW_STRIDE)   // 52224 floats = 208896 B

// ---------------- device scratch ----------------
__device__ __align__(256) float g_xg[(size_t)512 * 64 * 3072];  // 402 MB
__device__ __align__(256) float g_part[(size_t)8 * 64 * 2048];
__device__ __align__(256) float g_h0[64 * 1024];
__device__ __align__(256) float g_h1[64 * 1024];
__device__ __align__(256) float g_hr0[64 * 1024];
__device__ __align__(256) float g_hr1[64 * 1024];
__device__ __align__(256) float g_zs0[64 * 1024];
__device__ __align__(256) float g_zs1[64 * 1024];
__device__ unsigned g_cnt[4][16];
__device__ unsigned g_bar_cnt;
__device__ unsigned g_bar_gen;

// ---------------- helpers ----------------
__device__ __forceinline__ void cp16(void* s, const void* g) {
    uint32_t sa = (uint32_t)__cvta_generic_to_shared(s);
    asm volatile("cp.async.cg.shared.global [%0], [%1], 16;" :: "r"(sa), "l"(g));
}
__device__ __forceinline__ float sigmoidf_(float x) { return 1.f / (1.f + expf(-x)); }

__device__ __forceinline__ float2 tf32split(float v) {
    uint32_t hu;
    asm("cvt.rna.tf32.f32 %0, %1;" : "=r"(hu) : "f"(v));
    float hi = __uint_as_float(hu);
    float lo = v - hi;
    uint32_t lu;
    asm("cvt.rna.tf32.f32 %0, %1;" : "=r"(lu) : "f"(lo));
    return make_float2(hi, __uint_as_float(lu));
}

__device__ __forceinline__ void mma8(float& d0, float& d1, float& d2, float& d3,
                                     const uint32_t a[4], uint32_t b0, uint32_t b1) {
    asm volatile(
        "mma.sync.aligned.m16n8k8.row.col.f32.tf32.tf32.f32 "
        "{%0,%1,%2,%3},{%4,%5,%6,%7},{%8,%9},{%0,%1,%2,%3};"
        : "+f"(d0), "+f"(d1), "+f"(d2), "+f"(d3)
        : "r"(a[0]), "r"(a[1]), "r"(a[2]), "r"(a[3]), "r"(b0), "r"(b1));
}

__device__ __forceinline__ unsigned ld_acq(unsigned* p) {
    unsigned v;
    asm volatile("ld.acquire.gpu.b32 %0, [%1];" : "=r"(v) : "l"(p));
    return v;
}
__device__ __forceinline__ void st_rel(unsigned* p, unsigned v) {
    asm volatile("st.release.gpu.b32 [%0], %1;" :: "l"(p), "r"(v));
}

__device__ __forceinline__ void gridsync() {
    __syncthreads();
    if (threadIdx.x == 0) {
        unsigned gen = ld_acq(&g_bar_gen);
        __threadfence();
        unsigned n = atomicAdd(&g_bar_cnt, 1u);
        if (n == GRID - 1) {
            g_bar_cnt = 0;
            st_rel(&g_bar_gen, gen + 1u);
        } else {
            while (ld_acq(&g_bar_gen) == gen) { }
        }
    }
    __syncthreads();
}

// ---------------- GEMM core: 64(batch) x 128(feat) x [k0, k0+nchunks*KC) ----
// A operand fp32 [b][k] rows (A1 for k<kSplit else A2); W fp32 [n][k] rows.
// tf32 hi/lo split done cooperatively into pair buffers per chunk.
__device__ __forceinline__ void gemm_core(
    float* sm,
    const float* A1, int ldA1, const float* A2, int ldA2, int kSplit,
    const float* Wb, int ldW,
    int k0, int nchunks, float acc[8][4])
{
    float* rawA  = sm + SM_RAWA;
    float* rawW  = sm + SM_RAWW;
    float* pairA = sm + SM_PAIRA;
    float* pairW = sm + SM_PAIRW;
    const int t = threadIdx.x;
    const int w = t >> 5, l = t & 31;
    const int mb = (w & 3) * 16 + (l >> 2);
    const int fh = (w >> 2) * 64 + (l >> 2);
    const int kq = l & 3;

    // prefetch chunk 0 into buffer 0
    {
        const float* a = (k0 < kSplit) ? (A1 + k0) : (A2 + (k0 - kSplit));
        int lda = (k0 < kSplit) ? ldA1 : ldA2;
        #pragma unroll
        for (int i = 0; i < 4; i++) {
            int idx = t + i * 256, r = idx >> 4, c4 = idx & 15;
            cp16(rawA + r * RA_STRIDE + c4 * 4, a + (size_t)r * lda + c4 * 4);
        }
        const float* wsrc = Wb + k0;
        #pragma unroll
        for (int i = 0; i < 8; i++) {
            int idx = t + i * 256, r = idx >> 4, c4 = idx & 15;
            cp16(rawW + r * RW_STRIDE + c4 * 4, wsrc + (size_t)r * ldW + c4 * 4);
        }
        asm volatile("cp.async.commit_group;" ::: "memory");
    }

    for (int c = 0; c < nchunks; c++) {
        const int buf = c & 1;
        if (c + 1 < nchunks) {
            int k = k0 + (c + 1) * KC;
            const float* a = (k < kSplit) ? (A1 + k) : (A2 + (k - kSplit));
            int lda = (k < kSplit) ? ldA1 : ldA2;
            float* dA = rawA + (buf ^ 1) * (64 * RA_STRIDE);
            float* dW = rawW + (buf ^ 1) * (128 * RW_STRIDE);
            #pragma unroll
            for (int i = 0; i < 4; i++) {
                int idx = t + i * 256, r = idx >> 4, c4 = idx & 15;
                cp16(dA + r * RA_STRIDE + c4 * 4, a + (size_t)r * lda + c4 * 4);
            }
            const float* wsrc = Wb + k;
            #pragma unroll
            for (int i = 0; i < 8; i++) {
                int idx = t + i * 256, r = idx >> 4, c4 = idx & 15;
                cp16(dW + r * RW_STRIDE + c4 * 4, wsrc + (size_t)r * ldW + c4 * 4);
            }
            asm volatile("cp.async.commit_group;" ::: "memory");
            asm volatile("cp.async.wait_group 1;" ::: "memory");
        } else {
            asm volatile("cp.async.wait_group 0;" ::: "memory");
        }
        __syncthreads();

        // cooperative tf32 split: raw -> (hi,lo) pairs
        const float* rA = rawA + buf * (64 * RA_STRIDE);
        const float* rW = rawW + buf * (128 * RW_STRIDE);
        #pragma unroll
        for (int i = 0; i < 16; i++) {
            int idx = t + i * 256, r = idx >> 6, k = idx & 63;
            *(float2*)&pairA[r * PA_STRIDE + 2 * k] = tf32split(rA[r * RA_STRIDE + k]);
        }
        #pragma unroll
        for (int i = 0; i < 32; i++) {
            int idx = t + i * 256, r = idx >> 6, k = idx & 63;
            *(float2*)&pairW[r * PW_STRIDE + 2 * k] = tf32split(rW[r * RW_STRIDE + k]);
        }
        __syncthreads();

        // mma loop
        #pragma unroll
        for (int q = 0; q < 8; q++) {
            uint32_t ah[4], al[4];
            #pragma unroll
            for (int e = 0; e < 4; e++) {
                float2 p = *(const float2*)&pairA[(mb + 8 * (e & 1)) * PA_STRIDE
                                                  + 2 * (q * 8 + kq + 4 * (e >> 1))];
                ah[e] = __float_as_uint(p.x);
                al[e] = __float_as_uint(p.y);
            }
            #pragma unroll
            for (int j = 0; j < 8; j++) {
                const float* wr = &pairW[(fh + j * 8) * PW_STRIDE + 2 * (q * 8 + kq)];
                float2 b0 = *(const float2*)(wr);
                float2 b1 = *(const float2*)(wr + 8);
                uint32_t bh0 = __float_as_uint(b0.x), bl0 = __float_as_uint(b0.y);
                uint32_t bh1 = __float_as_uint(b1.x), bl1 = __float_as_uint(b1.y);
                mma8(acc[j][0], acc[j][1], acc[j][2], acc[j][3], ah, bh0, bh1);
                mma8(acc[j][0], acc[j][1], acc[j][2], acc[j][3], ah, bl0, bl1);
                mma8(acc[j][0], acc[j][1], acc[j][2], acc[j][3], al, bh0, bh1);
            }
        }
        __syncthreads();
    }
}

// ---------------- x-projection precompute ----------------
__global__ void __launch_bounds__(256, 1) xproj_k(
    const float* __restrict__ x,
    const float* __restrict__ Wr0, const float* __restrict__ Wz0,
    const float* __restrict__ Wc0,
    const float* __restrict__ br0, const float* __restrict__ bz0,
    const float* __restrict__ bc0)
{
    extern __shared__ float sm[];
    const int ft = blockIdx.x;   // 0..23 (r:0-7, z:8-15, c:16-23)
    const int tt = blockIdx.y;   // timestep
    const float* Wb;
    const float* bb;
    if (ft < 8)       { Wb = Wr0 + (size_t)(ft * 128) * 1536;        bb = br0 + ft * 128; }
    else if (ft < 16) { Wb = Wz0 + (size_t)((ft - 8) * 128) * 1536;  bb = bz0 + (ft - 8) * 128; }
    else              { Wb = Wc0 + (size_t)((ft - 16) * 128) * 1536; bb = bc0 + (ft - 16) * 128; }
    const float* A = x + (size_t)tt * 512;   // row stride 512*512 per batch

    float acc[8][4];
    #pragma unroll
    for (int j = 0; j < 8; j++)
        #pragma unroll
        for (int e = 0; e < 4; e++) acc[j][e] = 0.f;

    gemm_core(sm, A, 512 * 512, A, 512 * 512, 1 << 30, Wb, 1536, 0, 8, acc);

    const int w = threadIdx.x >> 5, l = threadIdx.x & 31;
    const int m0 = (w & 3) * 16 + (l >> 2);
    const int c0 = (w >> 2) * 64 + 2 * (l & 3);
    float* og = g_xg + ((size_t)tt * 64) * 3072 + (size_t)ft * 128;
    #pragma unroll
    for (int j = 0; j < 8; j++) {
        int f = c0 + j * 8;
        float b0 = bb[f], b1 = bb[f + 1];
        *(float2*)&og[(size_t)m0 * 3072 + f]       = make_float2(acc[j][0] + b0, acc[j][1] + b1);
        *(float2*)&og[(size_t)(m0 + 8) * 3072 + f] = make_float2(acc[j][2] + b0, acc[j][3] + b1);
    }
}

// ---------------- persistent recurrence ----------------
__global__ void __launch_bounds__(256, 1) gru_persist(
    const float* __restrict__ Wr0, const float* __restrict__ Wz0,
    const float* __restrict__ Wc0,
    const float* __restrict__ Wr1, const float* __restrict__ Wz1,
    const float* __restrict__ Wc1,
    const float* __restrict__ br1, const float* __restrict__ bz1,
    const float* __restrict__ bc1,
    const float* __restrict__ Wreg, const float* __restrict__ breg,
    float* __restrict__ out)
{
    extern __shared__ float sm[];
    const int cta = blockIdx.x, tid = threadIdx.x;
    const int w = tid >> 5, l = tid & 31;
    const int ftA = cta >> 3, sA = cta & 7;    // phases A, C (N=2048)
    const int ftB = cta >> 4, sB = cta & 15;   // phases B, D (N=1024)

    // counter bases (read before any CTA can increment: pre-gridsync)
    __shared__ unsigned sbase[4];
    if (tid == 0) {
        sbase[0] = g_cnt[0][ftA];
        sbase[1] = g_cnt[1][ftB];
        sbase[2] = g_cnt[2][ftA];
        sbase[3] = g_cnt[3][ftB];
    }
    for (int i = cta * 256 + tid; i < 64 * 1024; i += GRID * 256) {
        g_h0[i] = 0.f;
        g_h1[i] = 0.f;
    }
    gridsync();
    const unsigned b0c = sbase[0], b1c = sbase[1], b2c = sbase[2], b3c = sbase[3];

    // epilogue index helpers
    const int m0 = (w & 3) * 16 + (l >> 2);
    const int c0 = (w >> 2) * 64 + 2 * (l & 3);
    // reduce A/C indices (1024 outputs: 4/thread)
    const int rmA = sA * 8 + (tid >> 5);
    const int rfA = (tid & 31) * 4;
    const int nfA = ftA * 128 + rfA;
    // reduce B/D indices (512 outputs: 2/thread)
    const int rmB = sB * 4 + (tid >> 6);
    const int rfB = (tid & 63) * 2;
    const int nfB = ftB * 128 + rfB;

    const float* WA_A = (ftA < 8) ? (Wr0 + (size_t)(ftA * 128) * 1536 + 512)
                                  : (Wz0 + (size_t)((ftA - 8) * 128) * 1536 + 512);
    const float* WA_C = (ftA < 8) ? (Wr1 + (size_t)(ftA * 128) * 2048)
                                  : (Wz1 + (size_t)((ftA - 8) * 128) * 2048);
    const float* WB_B = Wc0 + (size_t)(ftB * 128) * 1536 + 512;
    const float* WB_D = Wc1 + (size_t)(ftB * 128) * 2048;

    for (int t = 0; t < 512; t++) {
        const float* xgm = g_xg + (size_t)t * 64 * 3072;
        float acc[8][4];

        // ---- Phase A: gates0 r|z  (K=1024 over h0; 16 ft x 8 slices of 128)
        #pragma unroll
        for (int j = 0; j < 8; j++)
            #pragma unroll
            for (int e = 0; e < 4; e++) acc[j][e] = 0.f;
        gemm_core(sm, g_h0, 1024, g_h0, 1024, 1 << 30, WA_A, 1536, sA * 128, 2, acc);
        {
            float* pb = g_part + (size_t)sA * 64 * 2048 + (size_t)ftA * 128;
            #pragma unroll
            for (int j = 0; j < 8; j++) {
                *(float2*)&pb[(size_t)m0 * 2048 + c0 + j * 8]       = make_float2(acc[j][0], acc[j][1]);
                *(float2*)&pb[(size_t)(m0 + 8) * 2048 + c0 + j * 8] = make_float2(acc[j][2], acc[j][3]);
            }
        }
        __threadfence();
        __syncthreads();
        if (tid == 0) {
            atomicAdd(&g_cnt[0][ftA], 1u);
            while ((unsigned)(ld_acq(&g_cnt[0][ftA]) - b0c) < (unsigned)(t + 1) * 8u) { }
        }
        __syncthreads();
        {
            float4 s = make_float4(0.f, 0.f, 0.f, 0.f);
            #pragma unroll
            for (int sl = 0; sl < 8; sl++) {
                float4 a = *(const float4*)&g_part[((size_t)sl * 64 + rmA) * 2048 + nfA];
                s.x += a.x; s.y += a.y; s.z += a.z; s.w += a.w;
            }
            float4 xg = *(const float4*)&xgm[(size_t)rmA * 3072 + nfA];
            s.x = sigmoidf_(s.x + xg.x); s.y = sigmoidf_(s.y + xg.y);
            s.z = sigmoidf_(s.z + xg.z); s.w = sigmoidf_(s.w + xg.w);
            if (nfA < 1024) {
                float4 h = *(const float4*)&g_h0[rmA * 1024 + nfA];
                *(float4*)&g_hr0[rmA * 1024 + nfA] =
                    make_float4(h.x * s.x, h.y * s.y, h.z * s.z, h.w * s.w);
            } else {
                *(float4*)&g_zs0[rmA * 1024 + nfA - 1024] = s;
            }
        }
        gridsync();

        // ---- Phase B: candidate0  (K=1024 over hr0; 8 ft x 16 slices of 64)
        #pragma unroll
        for (int j = 0; j < 8; j++)
            #pragma unroll
            for (int e = 0; e < 4; e++) acc[j][e] = 0.f;
        gemm_core(sm, g_hr0, 1024, g_hr0, 1024, 1 << 30, WB_B, 1536, sB * 64, 1, acc);
        {
            float* pb = g_part + (size_t)sB * 64 * 1024 + (size_t)ftB * 128;
            #pragma unroll
            for (int j = 0; j < 8; j++) {
                *(float2*)&pb[(size_t)m0 * 1024 + c0 + j * 8]       = make_float2(acc[j][0], acc[j][1]);
                *(float2*)&pb[(size_t)(m0 + 8) * 1024 + c0 + j * 8] = make_float2(acc[j][2], acc[j][3]);
            }
        }
        __threadfence();
        __syncthreads();
        if (tid == 0) {
            atomicAdd(&g_cnt[1][ftB], 1u);
            while ((unsigned)(ld_acq(&g_cnt[1][ftB]) - b1c) < (unsigned)(t + 1) * 16u) { }
        }
        __syncthreads();
        {
            float2 s = make_float2(0.f, 0.f);
            #pragma unroll
            for (int sl = 0; sl < 16; sl++) {
                float2 a = *(const float2*)&g_part[((size_t)sl * 64 + rmB) * 1024 + nfB];
                s.x += a.x; s.y += a.y;
            }
            float2 xg = *(const float2*)&xgm[(size_t)rmB * 3072 + 2048 + nfB];
            float cx = tanhf(s.x + xg.x), cy = tanhf(s.y + xg.y);
            float2 z = *(const float2*)&g_zs0[rmB * 1024 + nfB];
            float2 h = *(const float2*)&g_h0[rmB * 1024 + nfB];
            *(float2*)&g_h0[rmB * 1024 + nfB] =
                make_float2(h.x * z.x + (1.f - z.x) * cx,
                            h.y * z.y + (1.f - z.y) * cy);
        }
        gridsync();

        // ---- Phase C: gates1 r|z  (K=2048 over [h0|h1]; 16 ft x 8 slices of 256)
        #pragma unroll
        for (int j = 0; j < 8; j++)
            #pragma unroll
            for (int e = 0; e < 4; e++) acc[j][e] = 0.f;
        gemm_core(sm, g_h0, 1024, g_h1, 1024, 1024, WA_C, 2048, sA * 256, 4, acc);
        {
            float* pb = g_part + (size_t)sA * 64 * 2048 + (size_t)ftA * 128;
            #pragma unroll
            for (int j = 0; j < 8; j++) {
                *(float2*)&pb[(size_t)m0 * 2048 + c0 + j * 8]       = make_float2(acc[j][0], acc[j][1]);
                *(float2*)&pb[(size_t)(m0 + 8) * 2048 + c0 + j * 8] = make_float2(acc[j][2], acc[j][3]);
            }
        }
        __threadfence();
        __syncthreads();
        if (tid == 0) {
            atomicAdd(&g_cnt[2][ftA], 1u);
            while ((unsigned)(ld_acq(&g_cnt[2][ftA]) - b2c) < (unsigned)(t + 1) * 8u) { }
        }
        __syncthreads();
        {
            float4 s = make_float4(0.f, 0.f, 0.f, 0.f);
            #pragma unroll
            for (int sl = 0; sl < 8; sl++) {
                float4 a = *(const float4*)&g_part[((size_t)sl * 64 + rmA) * 2048 + nfA];
                s.x += a.x; s.y += a.y; s.z += a.z; s.w += a.w;
            }
            if (nfA < 1024) {
                float4 b = *(const float4*)&br1[nfA];
                s.x = sigmoidf_(s.x + b.x); s.y = sigmoidf_(s.y + b.y);
                s.z = sigmoidf_(s.z + b.z); s.w = sigmoidf_(s.w + b.w);
                float4 h = *(const float4*)&g_h1[rmA * 1024 + nfA];
                *(float4*)&g_hr1[rmA * 1024 + nfA] =
                    make_float4(h.x * s.x, h.y * s.y, h.z * s.z, h.w * s.w);
            } else {
                float4 b = *(const float4*)&bz1[nfA - 1024];
                s.x = sigmoidf_(s.x + b.x); s.y = sigmoidf_(s.y + b.y);
                s.z = sigmoidf_(s.z + b.z); s.w = sigmoidf_(s.w + b.w);
                *(float4*)&g_zs1[rmA * 1024 + nfA - 1024] = s;
            }
        }
        gridsync();

        // ---- Phase D: candidate1  (K=2048 over [h0|hr1]; 8 ft x 16 slices of 128)
        #pragma unroll
        for (int j = 0; j < 8; j++)
            #pragma unroll
            for (int e = 0; e < 4; e++) acc[j][e] = 0.f;
        gemm_core(sm, g_h0, 1024, g_hr1, 1024, 1024, WB_D, 2048, sB * 128, 2, acc);
        {
            float* pb = g_part + (size_t)sB * 64 * 1024 + (size_t)ftB * 128;
            #pragma unroll
            for (int j = 0; j < 8; j++) {
                *(float2*)&pb[(size_t)m0 * 1024 + c0 + j * 8]       = make_float2(acc[j][0], acc[j][1]);
                *(float2*)&pb[(size_t)(m0 + 8) * 1024 + c0 + j * 8] = make_float2(acc[j][2], acc[j][3]);
            }
        }
        __threadfence();
        __syncthreads();
        if (tid == 0) {
            atomicAdd(&g_cnt[3][ftB], 1u);
            while ((unsigned)(ld_acq(&g_cnt[3][ftB]) - b3c) < (unsigned)(t + 1) * 16u) { }
        }
        __syncthreads();
        {
            float2 s = make_float2(0.f, 0.f);
            #pragma unroll
            for (int sl = 0; sl < 16; sl++) {
                float2 a = *(const float2*)&g_part[((size_t)sl * 64 + rmB) * 1024 + nfB];
                s.x += a.x; s.y += a.y;
            }
            float2 b = *(const float2*)&bc1[nfB];
            float cx = tanhf(s.x + b.x), cy = tanhf(s.y + b.y);
            float2 z = *(const float2*)&g_zs1[rmB * 1024 + nfB];
            float2 h = *(const float2*)&g_h1[rmB * 1024 + nfB];
            *(float2*)&g_h1[rmB * 1024 + nfB] =
                make_float2(h.x * z.x + (1.f - z.x) * cx,
                            h.y * z.y + (1.f - z.y) * cy);
        }
        gridsync();
    }

    // regressor
    if (cta == 0 && tid < 128) {
        int o = tid >> 6, m = tid & 63;
        const float* hr = g_h1 + (size_t)m * 1024;
        const float* wr = Wreg + (size_t)o * 1024;
        float s0 = 0.f, s1 = 0.f, s2 = 0.f, s3 = 0.f;
        #pragma unroll 4
        for (int n = 0; n < 1024; n += 4) {
            s0 += hr[n + 0] * wr[n + 0];
            s1 += hr[n + 1] * wr[n + 1];
            s2 += hr[n + 2] * wr[n + 2];
            s3 += hr[n + 3] * wr[n + 3];
        }
        out[m * 2 + o] = s0 + s1 + s2 + s3 + breg[o];
    }
}

// ---------------- host ----------------
extern "C" void kernel_launch(void* const* d_in, const int* in_sizes, int n_in,
                              void* d_out, int out_size)
{
    const float* x    = (const float*)d_in[0];
    const float* Wr0  = (const float*)d_in[1];
    const float* br0  = (const float*)d_in[2];
    const float* Wz0  = (const float*)d_in[3];
    const float* bz0  = (const float*)d_in[4];
    const float* Wc0  = (const float*)d_in[5];
    const float* bc0  = (const float*)d_in[6];
    const float* Wr1  = (const float*)d_in[7];
    const float* br1  = (const float*)d_in[8];
    const float* Wz1  = (const float*)d_in[9];
    const float* bz1  = (const float*)d_in[10];
    const float* Wc1  = (const float*)d_in[11];
    const float* bc1  = (const float*)d_in[12];
    const float* Wreg = (const float*)d_in[13];
    const float* breg = (const float*)d_in[14];

    const int smem_bytes = SM_TOTAL * (int)sizeof(float);   // 208896
    cudaFuncSetAttribute(xproj_k, cudaFuncAttributeMaxDynamicSharedMemorySize, smem_bytes);
    cudaFuncSetAttribute(gru_persist, cudaFuncAttributeMaxDynamicSharedMemorySize, smem_bytes);

    xproj_k<<<dim3(24, 512), 256, smem_bytes>>>(x, Wr0, Wz0, Wc0, br0, bz0, bc0);
    gru_persist<<<GRID, 256, smem_bytes>>>(Wr0, Wz0, Wc0, Wr1, Wz1, Wc1,
                                           br1, bz1, bc1, Wreg, breg, (float*)d_out);
}

// round 16
// speedup vs baseline: 1.1540x; 1.0043x over previous
#include <cuda_runtime.h>
#include <cstdint>
#include <cstddef>

// ----------------------------------------------------------------------------
// 2-layer GRU (inverted update), B=64, S=512, I=512, H=1024, O=2.
// Kernel 1 (xproj): xg[t][b][3072] = x_t @ [Wr0|Wz0|Wc0][:, :512].T + bias
// Kernel 2 (persist, 128 CTAs): 512 steps; per step 4 GEMM phases on the
// tensor pipe (mma.m16n8k8 tf32, 3-pass hi/lo split done post-LDS from fp32
// smem), per-tile epoch counters for gemm->reduce ordering, 4 grid barriers
// per step. Weights read directly from harness buffers ([n][k] native).
// Deterministic: fixed-order reductions, no float atomics.
// ----------------------------------------------------------------------------

#define GRID 128
#define KC 64
#define RA_STRIDE 68
#define RW_STRIDE 68
#define PA_STRIDE 136
#define PW_STRIDE 136

#define SM_RAWA  0
#define SM_RAWW  (2 * 64 * RA_STRIDE)
#define SM_PAIRA (SM_RAWW + 2 * 128 * RW_STRIDE)
#define SM_PAIRW (SM_PAIRA + 64 * PA_STRIDE)
#define SM_TOTAL (SM_PAIRW + 128 * PW_STRIDE)   // 52224 floats = 208896 B

// ---------------- device scratch ----------------
__device__ __align__(256) float g_xg[(size_t)512 * 64 * 3072];  // 402 MB
__device__ __align__(256) float g_part[(size_t)8 * 64 * 2048];
__device__ __align__(256) float g_h0[64 * 1024];
__device__ __align__(256) float g_h1[64 * 1024];
__device__ __align__(256) float g_hr0[64 * 1024];
__device__ __align__(256) float g_hr1[64 * 1024];
__device__ __align__(256) float g_zs0[64 * 1024];
__device__ __align__(256) float g_zs1[64 * 1024];
__device__ unsigned g_cnt[4][16];
__device__ unsigned g_bar_cnt;
__device__ unsigned g_bar_gen;

// ---------------- helpers ----------------
__device__ __forceinline__ void cp16(void* s, const void* g) {
    uint32_t sa = (uint32_t)__cvta_generic_to_shared(s);
    asm volatile("cp.async.cg.shared.global [%0], [%1], 16;" :: "r"(sa), "l"(g));
}
__device__ __forceinline__ float sigmoidf_(float x) { return 1.f / (1.f + expf(-x)); }

__device__ __forceinline__ float2 tf32split(float v) {
    uint32_t hu;
    asm("cvt.rna.tf32.f32 %0, %1;" : "=r"(hu) : "f"(v));
    float hi = __uint_as_float(hu);
    float lo = v - hi;
    uint32_t lu;
    asm("cvt.rna.tf32.f32 %0, %1;" : "=r"(lu) : "f"(lo));
    return make_float2(hi, __uint_as_float(lu));
}

__device__ __forceinline__ void mma8(float& d0, float& d1, float& d2, float& d3,
                                     const uint32_t a[4], uint32_t b0, uint32_t b1) {
    asm volatile(
        "mma.sync.aligned.m16n8k8.row.col.f32.tf32.tf32.f32 "
        "{%0,%1,%2,%3},{%4,%5,%6,%7},{%8,%9},{%0,%1,%2,%3};"
        : "+f"(d0), "+f"(d1), "+f"(d2), "+f"(d3)
        : "r"(a[0]), "r"(a[1]), "r"(a[2]), "r"(a[3]), "r"(b0), "r"(b1));
}

__device__ __forceinline__ unsigned ld_acq(unsigned* p) {
    unsigned v;
    asm volatile("ld.acquire.gpu.b32 %0, [%1];" : "=r"(v) : "l"(p));
    return v;
}
__device__ __forceinline__ void st_rel(unsigned* p, unsigned v) {
    asm volatile("st.release.gpu.b32 [%0], %1;" :: "l"(p), "r"(v));
}

__device__ __forceinline__ void gridsync() {
    __syncthreads();
    if (threadIdx.x == 0) {
        unsigned gen = ld_acq(&g_bar_gen);
        __threadfence();
        unsigned n = atomicAdd(&g_bar_cnt, 1u);
        if (n == GRID - 1) {
            g_bar_cnt = 0;
            st_rel(&g_bar_gen, gen + 1u);
        } else {
            while (ld_acq(&g_bar_gen) == gen) { }
        }
    }
    __syncthreads();
}

// ---------------- GEMM core: 64(batch) x 128(feat) x [k0, k0+nchunks*KC) ----
// A operand fp32 [b][k] rows (A1 for k<kSplit else A2); W fp32 [n][k] rows.
// tf32 hi/lo split done cooperatively into pair buffers per chunk.
__device__ __forceinline__ void gemm_core(
    float* sm,
    const float* A1, int ldA1, const float* A2, int ldA2, int kSplit,
    const float* Wb, int ldW,
    int k0, int nchunks, float acc[8][4])
{
    float* rawA  = sm + SM_RAWA;
    float* rawW  = sm + SM_RAWW;
    float* pairA = sm + SM_PAIRA;
    float* pairW = sm + SM_PAIRW;
    const int t = threadIdx.x;
    const int w = t >> 5, l = t & 31;
    const int mb = (w & 3) * 16 + (l >> 2);
    const int fh = (w >> 2) * 64 + (l >> 2);
    const int kq = l & 3;

    // prefetch chunk 0 into buffer 0
    {
        const float* a = (k0 < kSplit) ? (A1 + k0) : (A2 + (k0 - kSplit));
        int lda = (k0 < kSplit) ? ldA1 : ldA2;
        #pragma unroll
        for (int i = 0; i < 4; i++) {
            int idx = t + i * 256, r = idx >> 4, c4 = idx & 15;
            cp16(rawA + r * RA_STRIDE + c4 * 4, a + (size_t)r * lda + c4 * 4);
        }
        const float* wsrc = Wb + k0;
        #pragma unroll
        for (int i = 0; i < 8; i++) {
            int idx = t + i * 256, r = idx >> 4, c4 = idx & 15;
            cp16(rawW + r * RW_STRIDE + c4 * 4, wsrc + (size_t)r * ldW + c4 * 4);
        }
        asm volatile("cp.async.commit_group;" ::: "memory");
    }

    for (int c = 0; c < nchunks; c++) {
        const int buf = c & 1;
        if (c + 1 < nchunks) {
            int k = k0 + (c + 1) * KC;
            const float* a = (k < kSplit) ? (A1 + k) : (A2 + (k - kSplit));
            int lda = (k < kSplit) ? ldA1 : ldA2;
            float* dA = rawA + (buf ^ 1) * (64 * RA_STRIDE);
            float* dW = rawW + (buf ^ 1) * (128 * RW_STRIDE);
            #pragma unroll
            for (int i = 0; i < 4; i++) {
                int idx = t + i * 256, r = idx >> 4, c4 = idx & 15;
                cp16(dA + r * RA_STRIDE + c4 * 4, a + (size_t)r * lda + c4 * 4);
            }
            const float* wsrc = Wb + k;
            #pragma unroll
            for (int i = 0; i < 8; i++) {
                int idx = t + i * 256, r = idx >> 4, c4 = idx & 15;
                cp16(dW + r * RW_STRIDE + c4 * 4, wsrc + (size_t)r * ldW + c4 * 4);
            }
            asm volatile("cp.async.commit_group;" ::: "memory");
            asm volatile("cp.async.wait_group 1;" ::: "memory");
        } else {
            asm volatile("cp.async.wait_group 0;" ::: "memory");
        }
        __syncthreads();

        // cooperative tf32 split: raw -> (hi,lo) pairs
        const float* rA = rawA + buf * (64 * RA_STRIDE);
        const float* rW = rawW + buf * (128 * RW_STRIDE);
        #pragma unroll
        for (int i = 0; i < 16; i++) {
            int idx = t + i * 256, r = idx >> 6, k = idx & 63;
            *(float2*)&pairA[r * PA_STRIDE + 2 * k] = tf32split(rA[r * RA_STRIDE + k]);
        }
        #pragma unroll
        for (int i = 0; i < 32; i++) {
            int idx = t + i * 256, r = idx >> 6, k = idx & 63;
            *(float2*)&pairW[r * PW_STRIDE + 2 * k] = tf32split(rW[r * RW_STRIDE + k]);
        }
        __syncthreads();

        // mma loop
        #pragma unroll
        for (int q = 0; q < 8; q++) {
            uint32_t ah[4], al[4];
            #pragma unroll
            for (int e = 0; e < 4; e++) {
                float2 p = *(const float2*)&pairA[(mb + 8 * (e & 1)) * PA_STRIDE
                                                  + 2 * (q * 8 + kq + 4 * (e >> 1))];
                ah[e] = __float_as_uint(p.x);
                al[e] = __float_as_uint(p.y);
            }
            #pragma unroll
            for (int j = 0; j < 8; j++) {
                const float* wr = &pairW[(fh + j * 8) * PW_STRIDE + 2 * (q * 8 + kq)];
                float2 b0 = *(const float2*)(wr);
                float2 b1 = *(const float2*)(wr + 8);
                uint32_t bh0 = __float_as_uint(b0.x), bl0 = __float_as_uint(b0.y);
                uint32_t bh1 = __float_as_uint(b1.x), bl1 = __float_as_uint(b1.y);
                mma8(acc[j][0], acc[j][1], acc[j][2], acc[j][3], ah, bh0, bh1);
                mma8(acc[j][0], acc[j][1], acc[j][2], acc[j][3], ah, bl0, bl1);
                mma8(acc[j][0], acc[j][1], acc[j][2], acc[j][3], al, bh0, bh1);
            }
        }
        __syncthreads();
    }
}

// ---------------- x-projection precompute ----------------
__global__ void __launch_bounds__(256, 1) xproj_k(
    const float* __restrict__ x,
    const float* __restrict__ Wr0, const float* __restrict__ Wz0,
    const float* __restrict__ Wc0,
    const float* __restrict__ br0, const float* __restrict__ bz0,
    const float* __restrict__ bc0)
{
    extern __shared__ float sm[];
    const int ft = blockIdx.x;   // 0..23 (r:0-7, z:8-15, c:16-23)
    const int tt = blockIdx.y;   // timestep
    const float* Wb;
    const float* bb;
    if (ft < 8)       { Wb = Wr0 + (size_t)(ft * 128) * 1536;        bb = br0 + ft * 128; }
    else if (ft < 16) { Wb = Wz0 + (size_t)((ft - 8) * 128) * 1536;  bb = bz0 + (ft - 8) * 128; }
    else              { Wb = Wc0 + (size_t)((ft - 16) * 128) * 1536; bb = bc0 + (ft - 16) * 128; }
    const float* A = x + (size_t)tt * 512;   // row stride 512*512 per batch

    float acc[8][4];
    #pragma unroll
    for (int j = 0; j < 8; j++)
        #pragma unroll
        for (int e = 0; e < 4; e++) acc[j][e] = 0.f;

    gemm_core(sm, A, 512 * 512, A, 512 * 512, 1 << 30, Wb, 1536, 0, 8, acc);

    const int w = threadIdx.x >> 5, l = threadIdx.x & 31;
    const int m0 = (w & 3) * 16 + (l >> 2);
    const int c0 = (w >> 2) * 64 + 2 * (l & 3);
    float* og = g_xg + ((size_t)tt * 64) * 3072 + (size_t)ft * 128;
    #pragma unroll
    for (int j = 0; j < 8; j++) {
        int f = c0 + j * 8;
        float b0 = bb[f], b1 = bb[f + 1];
        *(float2*)&og[(size_t)m0 * 3072 + f]       = make_float2(acc[j][0] + b0, acc[j][1] + b1);
        *(float2*)&og[(size_t)(m0 + 8) * 3072 + f] = make_float2(acc[j][2] + b0, acc[j][3] + b1);
    }
}

// ---------------- persistent recurrence ----------------
__global__ void __launch_bounds__(256, 1) gru_persist(
    const float* __restrict__ Wr0, const float* __restrict__ Wz0,
    const float* __restrict__ Wc0,
    const float* __restrict__ Wr1, const float* __restrict__ Wz1,
    const float* __restrict__ Wc1,
    const float* __restrict__ br1, const float* __restrict__ bz1,
    const float* __restrict__ bc1,
    const float* __restrict__ Wreg, const float* __restrict__ breg,
    float* __restrict__ out)
{
    extern __shared__ float sm[];
    const int cta = blockIdx.x, tid = threadIdx.x;
    const int w = tid >> 5, l = tid & 31;
    const int ftA = cta >> 3, sA = cta & 7;    // phases A, C (N=2048)
    const int ftB = cta >> 4, sB = cta & 15;   // phases B, D (N=1024)

    // counter bases (read before any CTA can increment: pre-gridsync)
    __shared__ unsigned sbase[4];
    if (tid == 0) {
        sbase[0] = g_cnt[0][ftA];
        sbase[1] = g_cnt[1][ftB];
        sbase[2] = g_cnt[2][ftA];
        sbase[3] = g_cnt[3][ftB];
    }
    for (int i = cta * 256 + tid; i < 64 * 1024; i += GRID * 256) {
        g_h0[i] = 0.f;
        g_h1[i] = 0.f;
    }
    gridsync();
    const unsigned b0c = sbase[0], b1c = sbase[1], b2c = sbase[2], b3c = sbase[3];

    // epilogue index helpers
    const int m0 = (w & 3) * 16 + (l >> 2);
    const int c0 = (w >> 2) * 64 + 2 * (l & 3);
    // reduce A/C indices (1024 outputs: 4/thread)
    const int rmA = sA * 8 + (tid >> 5);
    const int rfA = (tid & 31) * 4;
    const int nfA = ftA * 128 + rfA;
    // reduce B/D indices (512 outputs: 2/thread)
    const int rmB = sB * 4 + (tid >> 6);
    const int rfB = (tid & 63) * 2;
    const int nfB = ftB * 128 + rfB;

    const float* WA_A = (ftA < 8) ? (Wr0 + (size_t)(ftA * 128) * 1536 + 512)
                                  : (Wz0 + (size_t)((ftA - 8) * 128) * 1536 + 512);
    const float* WA_C = (ftA < 8) ? (Wr1 + (size_t)(ftA * 128) * 2048)
                                  : (Wz1 + (size_t)((ftA - 8) * 128) * 2048);
    const float* WB_B = Wc0 + (size_t)(ftB * 128) * 1536 + 512;
    const float* WB_D = Wc1 + (size_t)(ftB * 128) * 2048;

    for (int t = 0; t < 512; t++) {
        const float* xgm = g_xg + (size_t)t * 64 * 3072;
        float acc[8][4];

        // ---- Phase A: gates0 r|z  (K=1024 over h0; 16 ft x 8 slices of 128)
        #pragma unroll
        for (int j = 0; j < 8; j++)
            #pragma unroll
            for (int e = 0; e < 4; e++) acc[j][e] = 0.f;
        gemm_core(sm, g_h0, 1024, g_h0, 1024, 1 << 30, WA_A, 1536, sA * 128, 2, acc);
        {
            float* pb = g_part + (size_t)sA * 64 * 2048 + (size_t)ftA * 128;
            #pragma unroll
            for (int j = 0; j < 8; j++) {
                *(float2*)&pb[(size_t)m0 * 2048 + c0 + j * 8]       = make_float2(acc[j][0], acc[j][1]);
                *(float2*)&pb[(size_t)(m0 + 8) * 2048 + c0 + j * 8] = make_float2(acc[j][2], acc[j][3]);
            }
        }
        __threadfence();
        __syncthreads();
        if (tid == 0) {
            atomicAdd(&g_cnt[0][ftA], 1u);
            while ((unsigned)(ld_acq(&g_cnt[0][ftA]) - b0c) < (unsigned)(t + 1) * 8u) { }
        }
        __syncthreads();
        {
            float4 s = make_float4(0.f, 0.f, 0.f, 0.f);
            #pragma unroll
            for (int sl = 0; sl < 8; sl++) {
                float4 a = *(const float4*)&g_part[((size_t)sl * 64 + rmA) * 2048 + nfA];
                s.x += a.x; s.y += a.y; s.z += a.z; s.w += a.w;
            }
            float4 xg = *(const float4*)&xgm[(size_t)rmA * 3072 + nfA];
            s.x = sigmoidf_(s.x + xg.x); s.y = sigmoidf_(s.y + xg.y);
            s.z = sigmoidf_(s.z + xg.z); s.w = sigmoidf_(s.w + xg.w);
            if (nfA < 1024) {
                float4 h = *(const float4*)&g_h0[rmA * 1024 + nfA];
                *(float4*)&g_hr0[rmA * 1024 + nfA] =
                    make_float4(h.x * s.x, h.y * s.y, h.z * s.z, h.w * s.w);
            } else {
                *(float4*)&g_zs0[rmA * 1024 + nfA - 1024] = s;
            }
        }
        gridsync();

        // ---- Phase B: candidate0  (K=1024 over hr0; 8 ft x 16 slices of 64)
        #pragma unroll
        for (int j = 0; j < 8; j++)
            #pragma unroll
            for (int e = 0; e < 4; e++) acc[j][e] = 0.f;
        gemm_core(sm, g_hr0, 1024, g_hr0, 1024, 1 << 30, WB_B, 1536, sB * 64, 1, acc);
        {
            float* pb = g_part + (size_t)sB * 64 * 1024 + (size_t)ftB * 128;
            #pragma unroll
            for (int j = 0; j < 8; j++) {
                *(float2*)&pb[(size_t)m0 * 1024 + c0 + j * 8]       = make_float2(acc[j][0], acc[j][1]);
                *(float2*)&pb[(size_t)(m0 + 8) * 1024 + c0 + j * 8] = make_float2(acc[j][2], acc[j][3]);
            }
        }
        __threadfence();
        __syncthreads();
        if (tid == 0) {
            atomicAdd(&g_cnt[1][ftB], 1u);
            while ((unsigned)(ld_acq(&g_cnt[1][ftB]) - b1c) < (unsigned)(t + 1) * 16u) { }
        }
        __syncthreads();
        {
            float2 s = make_float2(0.f, 0.f);
            #pragma unroll
            for (int sl = 0; sl < 16; sl++) {
                float2 a = *(const float2*)&g_part[((size_t)sl * 64 + rmB) * 1024 + nfB];
                s.x += a.x; s.y += a.y;
            }
            float2 xg = *(const float2*)&xgm[(size_t)rmB * 3072 + 2048 + nfB];
            float cx = tanhf(s.x + xg.x), cy = tanhf(s.y + xg.y);
            float2 z = *(const float2*)&g_zs0[rmB * 1024 + nfB];
            float2 h = *(const float2*)&g_h0[rmB * 1024 + nfB];
            *(float2*)&g_h0[rmB * 1024 + nfB] =
                make_float2(h.x * z.x + (1.f - z.x) * cx,
                            h.y * z.y + (1.f - z.y) * cy);
        }
        gridsync();

        // ---- Phase C: gates1 r|z  (K=2048 over [h0|h1]; 16 ft x 8 slices of 256)
        #pragma unroll
        for (int j = 0; j < 8; j++)
            #pragma unroll
            for (int e = 0; e < 4; e++) acc[j][e] = 0.f;
        gemm_core(sm, g_h0, 1024, g_h1, 1024, 1024, WA_C, 2048, sA * 256, 4, acc);
        {
            float* pb = g_part + (size_t)sA * 64 * 2048 + (size_t)ftA * 128;
            #pragma unroll
            for (int j = 0; j < 8; j++) {
                *(float2*)&pb[(size_t)m0 * 2048 + c0 + j * 8]       = make_float2(acc[j][0], acc[j][1]);
                *(float2*)&pb[(size_t)(m0 + 8) * 2048 + c0 + j * 8] = make_float2(acc[j][2], acc[j][3]);
            }
        }
        __threadfence();
        __syncthreads();
        if (tid == 0) {
            atomicAdd(&g_cnt[2][ftA], 1u);
            while ((unsigned)(ld_acq(&g_cnt[2][ftA]) - b2c) < (unsigned)(t + 1) * 8u) { }
        }
        __syncthreads();
        {
            float4 s = make_float4(0.f, 0.f, 0.f, 0.f);
            #pragma unroll
            for (int sl = 0; sl < 8; sl++) {
                float4 a = *(const float4*)&g_part[((size_t)sl * 64 + rmA) * 2048 + nfA];
                s.x += a.x; s.y += a.y; s.z += a.z; s.w += a.w;
            }
            if (nfA < 1024) {
                float4 b = *(const float4*)&br1[nfA];
                s.x = sigmoidf_(s.x + b.x); s.y = sigmoidf_(s.y + b.y);
                s.z = sigmoidf_(s.z + b.z); s.w = sigmoidf_(s.w + b.w);
                float4 h = *(const float4*)&g_h1[rmA * 1024 + nfA];
                *(float4*)&g_hr1[rmA * 1024 + nfA] =
                    make_float4(h.x * s.x, h.y * s.y, h.z * s.z, h.w * s.w);
            } else {
                float4 b = *(const float4*)&bz1[nfA - 1024];
                s.x = sigmoidf_(s.x + b.x); s.y = sigmoidf_(s.y + b.y);
                s.z = sigmoidf_(s.z + b.z); s.w = sigmoidf_(s.w + b.w);
                *(float4*)&g_zs1[rmA * 1024 + nfA - 1024] = s;
            }
        }
        gridsync();

        // ---- Phase D: candidate1  (K=2048 over [h0|hr1]; 8 ft x 16 slices of 128)
        #pragma unroll
        for (int j = 0; j < 8; j++)
            #pragma unroll
            for (int e = 0; e < 4; e++) acc[j][e] = 0.f;
        gemm_core(sm, g_h0, 1024, g_hr1, 1024, 1024, WB_D, 2048, sB * 128, 2, acc);
        {
            float* pb = g_part + (size_t)sB * 64 * 1024 + (size_t)ftB * 128;
            #pragma unroll
            for (int j = 0; j < 8; j++) {
                *(float2*)&pb[(size_t)m0 * 1024 + c0 + j * 8]       = make_float2(acc[j][0], acc[j][1]);
                *(float2*)&pb[(size_t)(m0 + 8) * 1024 + c0 + j * 8] = make_float2(acc[j][2], acc[j][3]);
            }
        }
        __threadfence();
        __syncthreads();
        if (tid == 0) {
            atomicAdd(&g_cnt[3][ftB], 1u);
            while ((unsigned)(ld_acq(&g_cnt[3][ftB]) - b3c) < (unsigned)(t + 1) * 16u) { }
        }
        __syncthreads();
        {
            float2 s = make_float2(0.f, 0.f);
            #pragma unroll
            for (int sl = 0; sl < 16; sl++) {
                float2 a = *(const float2*)&g_part[((size_t)sl * 64 + rmB) * 1024 + nfB];
                s.x += a.x; s.y += a.y;
            }
            float2 b = *(const float2*)&bc1[nfB];
            float cx = tanhf(s.x + b.x), cy = tanhf(s.y + b.y);
            float2 z = *(const float2*)&g_zs1[rmB * 1024 + nfB];
            float2 h = *(const float2*)&g_h1[rmB * 1024 + nfB];
            *(float2*)&g_h1[rmB * 1024 + nfB] =
                make_float2(h.x * z.x + (1.f - z.x) * cx,
                            h.y * z.y + (1.f - z.y) * cy);
        }
        gridsync();
    }

    // regressor
    if (cta == 0 && tid < 128) {
        int o = tid >> 6, m = tid & 63;
        const float* hr = g_h1 + (size_t)m * 1024;
        const float* wr = Wreg + (size_t)o * 1024;
        float s0 = 0.f, s1 = 0.f, s2 = 0.f, s3 = 0.f;
        #pragma unroll 4
        for (int n = 0; n < 1024; n += 4) {
            s0 += hr[n + 0] * wr[n + 0];
            s1 += hr[n + 1] * wr[n + 1];
            s2 += hr[n + 2] * wr[n + 2];
            s3 += hr[n + 3] * wr[n + 3];
        }
        out[m * 2 + o] = s0 + s1 + s2 + s3 + breg[o];
    }
}

// ---------------- host ----------------
extern "C" void kernel_launch(void* const* d_in, const int* in_sizes, int n_in,
                              void* d_out, int out_size)
{
    const float* x    = (const float*)d_in[0];
    const float* Wr0  = (const float*)d_in[1];
    const float* br0  = (const float*)d_in[2];
    const float* Wz0  = (const float*)d_in[3];
    const float* bz0  = (const float*)d_in[4];
    const float* Wc0  = (const float*)d_in[5];
    const float* bc0  = (const float*)d_in[6];
    const float* Wr1  = (const float*)d_in[7];
    const float* br1  = (const float*)d_in[8];
    const float* Wz1  = (const float*)d_in[9];
    const float* bz1  = (const float*)d_in[10];
    const float* Wc1  = (const float*)d_in[11];
    const float* bc1  = (const float*)d_in[12];
    const float* Wreg = (const float*)d_in[13];
    const float* breg = (const float*)d_in[14];

    const int smem_bytes = SM_TOTAL * (int)sizeof(float);   // 208896
    cudaFuncSetAttribute(xproj_k, cudaFuncAttributeMaxDynamicSharedMemorySize, smem_bytes);
    cudaFuncSetAttribute(gru_persist, cudaFuncAttributeMaxDynamicSharedMemorySize, smem_bytes);

    xproj_k<<<dim3(24, 512), 256, smem_bytes>>>(x, Wr0, Wz0, Wc0, br0, bz0, bc0);
    gru_persist<<<GRID, 256, smem_bytes>>>(Wr0, Wz0, Wc0, Wr1, Wz1, Wc1,
                                           br1, bz1, bc1, Wreg, breg, (float*)d_out);
}